// round 10
// baseline (speedup 1.0000x reference)
#include <cuda_runtime.h>
#include <cuda_fp16.h>

// ROIAlign(7x7, sr=2) + global avg pool, separable-weight formulation with
// shared-memory feature tiling.
//
// out[roi,ch] = sum_r a[r] * sum_c b[c] * F[bi,ch,r,c]; a/b are the y/x
// bilinear weight marginals (b pre-scaled by 1/196).
//
// R9 (= R8 with sm_100-legal reductions): two-kernel restructure.
//  K1 setup: per-ROI marginals a[128]/b[192] (exact fp16-rounded corner math)
//     + bbox meta into __device__ scratch; zero output feats; write gt.
//  K2 main: grid (16 row-strips, 32 ch-blocks, 4 batch). Each block stages an
//     8ch x 8row x 128col tile in smem (feature map read from global exactly
//     once overall), lists intersecting ROIs, and each warp computes all 8
//     channels for its ROIs from smem (LDS.128 with constant channel offsets).
//     Partial sums accumulate into out via atomicAdd across strips.

#define C_CH   256
#define HWD    128
#define RS     8            // rows per strip
#define CB     8            // channels per block
#define TCOLS  132          // padded tile row (bank-shift across rows)
#define NTHREADS 256

__device__ __align__(16) float g_a[512 * 128];
__device__ __align__(16) float g_b[512 * 192];
__device__ int4 g_meta[512];     // {bi, rlo, rhi, base | nch<<8}

// ---------------------------------------------------------------------------
// Setup: one 32-thread block per ROI.
// ---------------------------------------------------------------------------
__global__ void roi_setup_kernel(const float* __restrict__ rois,
                                 float* __restrict__ out, int n_rois)
{
    __shared__ float sa[128];
    __shared__ float sb[192];
    __shared__ int rlo_s, rhi_s, clo_s, chi_s;

    const int roi  = blockIdx.x;
    const int lane = threadIdx.x;

    if (lane == 0) { rlo_s = 1 << 30; rhi_s = -1; clo_s = 1 << 30; chi_s = -1; }
    for (int i = lane; i < 192; i += 32) { if (i < 128) sa[i] = 0.f; sb[i] = 0.f; }
    __syncwarp();

    // Lanes 0..13 = 14 y-samples, lanes 16..29 = 14 x-samples.
    const bool isY = (lane < 14);
    const bool isX = (lane >= 16 && lane < 30);
    if (isY || isX) {
        const int s = isY ? lane : lane - 16;
        const float cx = rois[roi * 6 + 2];
        const float cy = rois[roi * 6 + 3];
        const float w  = rois[roi * 6 + 4];
        const float h  = rois[roi * 6 + 5];
        // Reference rounds the scaled corners through fp16.
        const float x1 = __half2float(__float2half_rn((cx - 0.5f * w) * 128.f));
        const float x2 = __half2float(__float2half_rn((cx + 0.5f * w) * 128.f));
        const float y1 = __half2float(__float2half_rn((cy - 0.5f * h) * 128.f));
        const float y2 = __half2float(__float2half_rn((cy + 0.5f * h) * 128.f));
        const float rw = fmaxf(x2 - x1, 1.f);
        const float rh = fmaxf(y2 - y1, 1.f);

        const float off   = 0.25f + 0.5f * (float)s;   // p + (sub+0.5)/2
        const float start = isY ? y1 : x1;
        const float ext   = isY ? rh : rw;
        const float coord = start + off * (ext / 7.f);

        if (coord > -1.f && coord < 128.f) {
            const float cl = fminf(fmaxf(coord, 0.f), 127.f);
            const int   i0 = (int)floorf(cl);
            const int   i1 = min(i0 + 1, HWD - 1);
            const float l  = cl - (float)i0;
            const float hi = 1.f - l;
            if (isY) {
                atomicAdd(&sa[i0], hi);
                atomicAdd(&sa[i1], l);
                atomicMin(&rlo_s, i0);
                atomicMax(&rhi_s, i1);
            } else {
                const float inv = 1.f / 196.f;  // fold in the mean
                atomicAdd(&sb[i0], hi * inv);
                atomicAdd(&sb[i1], l * inv);
                atomicMin(&clo_s, i0);
                atomicMax(&chi_s, i1);
            }
        }
    }
    __syncwarp();

    for (int i = lane; i < 128; i += 32) g_a[roi * 128 + i] = sa[i];
    for (int i = lane; i < 192; i += 32) g_b[roi * 192 + i] = sb[i];
    // zero output feats (main kernel accumulates with atomics)
    for (int i = lane; i < C_CH; i += 32) out[(size_t)roi * C_CH + i] = 0.f;

    if (lane == 0) {
        out[(size_t)n_rois * C_CH + roi] = rois[roi * 6 + 1];   // gt
        int base = 0, nch = 0;
        if (rhi_s >= rlo_s && chi_s >= clo_s) {
            base = clo_s & ~3;
            nch  = ((chi_s - base) >> 2) + 1;    // exact chunk count (<=14)
        }
        g_meta[roi] = make_int4((int)rois[roi * 6 + 0], rlo_s, rhi_s,
                                base | (nch << 8));
    }
}

// ---------------------------------------------------------------------------
// Main: tile-staged accumulation.
// ---------------------------------------------------------------------------
__global__ __launch_bounds__(NTHREADS, 4)
void roi_tile_kernel(const float* __restrict__ feat,
                     float* __restrict__ out, int n_rois)
{
    __shared__ __align__(16) float tile[CB][RS][TCOLS];
    __shared__ int list_sh[512];
    __shared__ int cnt_sh;

    const int tid = threadIdx.x;
    const int rs0 = blockIdx.x * RS;
    const int cb0 = blockIdx.y * CB;
    const int bi  = blockIdx.z;

    if (tid == 0) cnt_sh = 0;

    // Stage the 8ch x 8row x 128col tile (8 float4 per thread, coalesced).
    const float* fsrc = feat + ((size_t)bi * C_CH + cb0) * (HWD * HWD)
                             + (size_t)rs0 * HWD;
    #pragma unroll
    for (int k = 0; k < 8; ++k) {
        const int idx = tid + k * NTHREADS;       // 0..2047 float4 slots
        const int ch  = idx >> 8;
        const int r   = (idx >> 5) & 7;
        const int c4  = idx & 31;
        const float4 v = *(const float4*)(fsrc + (size_t)ch * (HWD * HWD)
                                               + r * HWD + c4 * 4);
        *(float4*)&tile[ch][r][c4 * 4] = v;
    }
    __syncthreads();

    // Build the list of ROIs intersecting this (batch, strip).
    for (int t = tid; t < n_rois; t += NTHREADS) {
        const int4 m = g_meta[t];
        const int nch = m.w >> 8;
        if (m.x == bi && nch > 0 && m.y <= rs0 + RS - 1 && m.z >= rs0) {
            const int p = atomicAdd(&cnt_sh, 1);
            if (p < 512) list_sh[p] = t;
        }
    }
    __syncthreads();

    const int warp = tid >> 5;
    const int lane = tid & 31;
    const int n = min(cnt_sh, 512);

    for (int li = warp; li < n; li += CB) {
        const int roi = list_sh[li];
        const int4 m = g_meta[roi];
        const int base = m.w & 0xff;
        const int nch  = m.w >> 8;
        const int r0 = max(m.y, rs0);
        const int r1 = min(m.z, rs0 + RS - 1);
        const int nrs = r1 - r0 + 1;

        const int ncp   = (nch <= 1) ? 1 : (1 << (32 - __clz(nch - 1)));
        const int logn  = 31 - __clz(ncp);
        const int rpi   = 32 >> logn;            // rows per iteration
        const int chunk = lane & (ncp - 1);
        const int rsub  = lane >> logn;

        const int colv = base + 4 * chunk;
        const float4 bw = *(const float4*)&g_b[roi * 192 + colv]; // 0 beyond chi
        const int ceff = min(colv, HWD - 4);     // weight is 0 there anyway

        const float* ap = &g_a[roi * 128 + r0];
        const char* tp = (const char*)&tile[0][0][0]
                       + ((size_t)(r0 - rs0) * TCOLS + ceff) * 4;

        float a0 = 0.f, a1 = 0.f, a2 = 0.f, a3 = 0.f;
        float a4 = 0.f, a5 = 0.f, a6 = 0.f, a7 = 0.f;
        #pragma unroll 1
        for (int i = rsub; i < nrs; i += rpi) {
            const float aw = __ldg(ap + i);
            const char* p = tp + (size_t)i * (TCOLS * 4);
            const float4 f0 = *(const float4*)(p);
            const float4 f1 = *(const float4*)(p + 1 * RS * TCOLS * 4);
            const float4 f2 = *(const float4*)(p + 2 * RS * TCOLS * 4);
            const float4 f3 = *(const float4*)(p + 3 * RS * TCOLS * 4);
            const float4 f4 = *(const float4*)(p + 4 * RS * TCOLS * 4);
            const float4 f5 = *(const float4*)(p + 5 * RS * TCOLS * 4);
            const float4 f6 = *(const float4*)(p + 6 * RS * TCOLS * 4);
            const float4 f7 = *(const float4*)(p + 7 * RS * TCOLS * 4);
            float s0 = bw.x * f0.x; s0 = fmaf(bw.y, f0.y, s0);
            s0 = fmaf(bw.z, f0.z, s0); s0 = fmaf(bw.w, f0.w, s0);
            float s1 = bw.x * f1.x; s1 = fmaf(bw.y, f1.y, s1);
            s1 = fmaf(bw.z, f1.z, s1); s1 = fmaf(bw.w, f1.w, s1);
            float s2 = bw.x * f2.x; s2 = fmaf(bw.y, f2.y, s2);
            s2 = fmaf(bw.z, f2.z, s2); s2 = fmaf(bw.w, f2.w, s2);
            float s3 = bw.x * f3.x; s3 = fmaf(bw.y, f3.y, s3);
            s3 = fmaf(bw.z, f3.z, s3); s3 = fmaf(bw.w, f3.w, s3);
            float s4 = bw.x * f4.x; s4 = fmaf(bw.y, f4.y, s4);
            s4 = fmaf(bw.z, f4.z, s4); s4 = fmaf(bw.w, f4.w, s4);
            float s5 = bw.x * f5.x; s5 = fmaf(bw.y, f5.y, s5);
            s5 = fmaf(bw.z, f5.z, s5); s5 = fmaf(bw.w, f5.w, s5);
            float s6 = bw.x * f6.x; s6 = fmaf(bw.y, f6.y, s6);
            s6 = fmaf(bw.z, f6.z, s6); s6 = fmaf(bw.w, f6.w, s6);
            float s7 = bw.x * f7.x; s7 = fmaf(bw.y, f7.y, s7);
            s7 = fmaf(bw.z, f7.z, s7); s7 = fmaf(bw.w, f7.w, s7);
            a0 = fmaf(aw, s0, a0);
            a1 = fmaf(aw, s1, a1);
            a2 = fmaf(aw, s2, a2);
            a3 = fmaf(aw, s3, a3);
            a4 = fmaf(aw, s4, a4);
            a5 = fmaf(aw, s5, a5);
            a6 = fmaf(aw, s6, a6);
            a7 = fmaf(aw, s7, a7);
        }

        // eight independent butterfly reductions (pipelined)
        #pragma unroll
        for (int o = 16; o; o >>= 1) {
            a0 += __shfl_xor_sync(0xffffffffu, a0, o);
            a1 += __shfl_xor_sync(0xffffffffu, a1, o);
            a2 += __shfl_xor_sync(0xffffffffu, a2, o);
            a3 += __shfl_xor_sync(0xffffffffu, a3, o);
            a4 += __shfl_xor_sync(0xffffffffu, a4, o);
            a5 += __shfl_xor_sync(0xffffffffu, a5, o);
            a6 += __shfl_xor_sync(0xffffffffu, a6, o);
            a7 += __shfl_xor_sync(0xffffffffu, a7, o);
        }

        if (lane == 0) {
            float* op = out + (size_t)roi * C_CH + cb0;
            atomicAdd(op + 0, a0);
            atomicAdd(op + 1, a1);
            atomicAdd(op + 2, a2);
            atomicAdd(op + 3, a3);
            atomicAdd(op + 4, a4);
            atomicAdd(op + 5, a5);
            atomicAdd(op + 6, a6);
            atomicAdd(op + 7, a7);
        }
    }
}

extern "C" void kernel_launch(void* const* d_in, const int* in_sizes, int n_in,
                              void* d_out, int out_size)
{
    const float* feat = (const float*)d_in[0];   // (4, 256, 128, 128) fp32
    const float* rois = (const float*)d_in[1];   // (N, 6) fp32
    float* out = (float*)d_out;

    const int n_rois = in_sizes[1] / 6;          // 512
    (void)n_in; (void)out_size;

    roi_setup_kernel<<<n_rois, 32>>>(rois, out, n_rois);

    dim3 grid(HWD / RS, C_CH / CB, 4);           // (16, 32, 4)
    roi_tile_kernel<<<grid, NTHREADS>>>(feat, out, n_rois);
}

// round 11
// speedup vs baseline: 1.0791x; 1.0791x over previous
#include <cuda_runtime.h>
#include <cuda_fp16.h>

// ROIAlign(7x7, sr=2) + global avg pool, separable-weight formulation with
// shared-memory feature tiling.
//
// out[roi,ch] = sum_r a[r] * sum_c b[c] * F[bi,ch,r,c]; a/b are the y/x
// bilinear weight marginals (b pre-scaled by 1/196).
//
// R10: rebalanced tile (16 rows x 4 channels, same 33KB). Per-ROI inner
// loop now runs ~3 iterations (vs <=2) before the reduction, halving the
// relative overhead; 4 accumulators halve the butterfly + atomic cost;
// lower register pressure + launch_bounds(256,5) lifts occupancy.

#define C_CH   256
#define HWD    128
#define RS     16           // rows per strip
#define CB     4            // channels per block
#define TCOLS  132          // padded tile row (33 granules == 1 mod 8)
#define NTHREADS 256

__device__ __align__(16) float g_a[512 * 128];
__device__ __align__(16) float g_b[512 * 192];
__device__ int4 g_meta[512];     // {bi, rlo, rhi, base | nch<<8}

// ---------------------------------------------------------------------------
// Setup: one 32-thread block per ROI.
// ---------------------------------------------------------------------------
__global__ void roi_setup_kernel(const float* __restrict__ rois,
                                 float* __restrict__ out, int n_rois)
{
    __shared__ float sa[128];
    __shared__ float sb[192];
    __shared__ int rlo_s, rhi_s, clo_s, chi_s;

    const int roi  = blockIdx.x;
    const int lane = threadIdx.x;

    if (lane == 0) { rlo_s = 1 << 30; rhi_s = -1; clo_s = 1 << 30; chi_s = -1; }
    for (int i = lane; i < 192; i += 32) { if (i < 128) sa[i] = 0.f; sb[i] = 0.f; }
    __syncwarp();

    // Lanes 0..13 = 14 y-samples, lanes 16..29 = 14 x-samples.
    const bool isY = (lane < 14);
    const bool isX = (lane >= 16 && lane < 30);
    if (isY || isX) {
        const int s = isY ? lane : lane - 16;
        const float cx = rois[roi * 6 + 2];
        const float cy = rois[roi * 6 + 3];
        const float w  = rois[roi * 6 + 4];
        const float h  = rois[roi * 6 + 5];
        // Reference rounds the scaled corners through fp16.
        const float x1 = __half2float(__float2half_rn((cx - 0.5f * w) * 128.f));
        const float x2 = __half2float(__float2half_rn((cx + 0.5f * w) * 128.f));
        const float y1 = __half2float(__float2half_rn((cy - 0.5f * h) * 128.f));
        const float y2 = __half2float(__float2half_rn((cy + 0.5f * h) * 128.f));
        const float rw = fmaxf(x2 - x1, 1.f);
        const float rh = fmaxf(y2 - y1, 1.f);

        const float off   = 0.25f + 0.5f * (float)s;   // p + (sub+0.5)/2
        const float start = isY ? y1 : x1;
        const float ext   = isY ? rh : rw;
        const float coord = start + off * (ext / 7.f);

        if (coord > -1.f && coord < 128.f) {
            const float cl = fminf(fmaxf(coord, 0.f), 127.f);
            const int   i0 = (int)floorf(cl);
            const int   i1 = min(i0 + 1, HWD - 1);
            const float l  = cl - (float)i0;
            const float hi = 1.f - l;
            if (isY) {
                atomicAdd(&sa[i0], hi);
                atomicAdd(&sa[i1], l);
                atomicMin(&rlo_s, i0);
                atomicMax(&rhi_s, i1);
            } else {
                const float inv = 1.f / 196.f;  // fold in the mean
                atomicAdd(&sb[i0], hi * inv);
                atomicAdd(&sb[i1], l * inv);
                atomicMin(&clo_s, i0);
                atomicMax(&chi_s, i1);
            }
        }
    }
    __syncwarp();

    for (int i = lane; i < 128; i += 32) g_a[roi * 128 + i] = sa[i];
    for (int i = lane; i < 192; i += 32) g_b[roi * 192 + i] = sb[i];
    // zero output feats (main kernel accumulates with atomics)
    for (int i = lane; i < C_CH; i += 32) out[(size_t)roi * C_CH + i] = 0.f;

    if (lane == 0) {
        out[(size_t)n_rois * C_CH + roi] = rois[roi * 6 + 1];   // gt
        int base = 0, nch = 0;
        if (rhi_s >= rlo_s && chi_s >= clo_s) {
            base = clo_s & ~3;
            nch  = ((chi_s - base) >> 2) + 1;    // exact chunk count (<=14)
        }
        g_meta[roi] = make_int4((int)rois[roi * 6 + 0], rlo_s, rhi_s,
                                base | (nch << 8));
    }
}

// ---------------------------------------------------------------------------
// Main: tile-staged accumulation.
// ---------------------------------------------------------------------------
__global__ __launch_bounds__(NTHREADS, 5)
void roi_tile_kernel(const float* __restrict__ feat,
                     float* __restrict__ out, int n_rois)
{
    __shared__ __align__(16) float tile[CB][RS][TCOLS];
    __shared__ int list_sh[512];
    __shared__ int cnt_sh;

    const int tid = threadIdx.x;
    const int rs0 = blockIdx.x * RS;
    const int cb0 = blockIdx.y * CB;
    const int bi  = blockIdx.z;

    if (tid == 0) cnt_sh = 0;

    // Stage the 4ch x 16row x 128col tile (8 float4 per thread, coalesced).
    const float* fsrc = feat + ((size_t)bi * C_CH + cb0) * (HWD * HWD)
                             + (size_t)rs0 * HWD;
    #pragma unroll
    for (int k = 0; k < 8; ++k) {
        const int idx = tid + k * NTHREADS;       // 0..2047 float4 slots
        const int ch  = idx >> 9;                 // 512 float4 per channel
        const int r   = (idx >> 5) & 15;
        const int c4  = idx & 31;
        const float4 v = *(const float4*)(fsrc + (size_t)ch * (HWD * HWD)
                                               + r * HWD + c4 * 4);
        *(float4*)&tile[ch][r][c4 * 4] = v;
    }
    __syncthreads();

    // Build the list of ROIs intersecting this (batch, strip).
    for (int t = tid; t < n_rois; t += NTHREADS) {
        const int4 m = g_meta[t];
        const int nch = m.w >> 8;
        if (m.x == bi && nch > 0 && m.y <= rs0 + RS - 1 && m.z >= rs0) {
            const int p = atomicAdd(&cnt_sh, 1);
            if (p < 512) list_sh[p] = t;
        }
    }
    __syncthreads();

    const int warp = tid >> 5;
    const int lane = tid & 31;
    const int n = min(cnt_sh, 512);

    for (int li = warp; li < n; li += 8) {
        const int roi = list_sh[li];
        const int4 m = g_meta[roi];
        const int base = m.w & 0xff;
        const int nch  = m.w >> 8;
        const int r0 = max(m.y, rs0);
        const int r1 = min(m.z, rs0 + RS - 1);
        const int nrs = r1 - r0 + 1;

        const int ncp   = (nch <= 1) ? 1 : (1 << (32 - __clz(nch - 1)));
        const int logn  = 31 - __clz(ncp);
        const int rpi   = 32 >> logn;            // rows per iteration
        const int chunk = lane & (ncp - 1);
        const int rsub  = lane >> logn;

        const int colv = base + 4 * chunk;
        const float4 bw = *(const float4*)&g_b[roi * 192 + colv]; // 0 beyond chi
        const int ceff = min(colv, HWD - 4);     // weight is 0 there anyway

        const float* ap = &g_a[roi * 128 + r0];
        const char* tp = (const char*)&tile[0][0][0]
                       + ((size_t)(r0 - rs0) * TCOLS + ceff) * 4;

        float a0 = 0.f, a1 = 0.f, a2 = 0.f, a3 = 0.f;
        #pragma unroll 1
        for (int i = rsub; i < nrs; i += rpi) {
            const float aw = __ldg(ap + i);
            const char* p = tp + (size_t)i * (TCOLS * 4);
            const float4 f0 = *(const float4*)(p);
            const float4 f1 = *(const float4*)(p + 1 * RS * TCOLS * 4);
            const float4 f2 = *(const float4*)(p + 2 * RS * TCOLS * 4);
            const float4 f3 = *(const float4*)(p + 3 * RS * TCOLS * 4);
            float s0 = bw.x * f0.x; s0 = fmaf(bw.y, f0.y, s0);
            s0 = fmaf(bw.z, f0.z, s0); s0 = fmaf(bw.w, f0.w, s0);
            float s1 = bw.x * f1.x; s1 = fmaf(bw.y, f1.y, s1);
            s1 = fmaf(bw.z, f1.z, s1); s1 = fmaf(bw.w, f1.w, s1);
            float s2 = bw.x * f2.x; s2 = fmaf(bw.y, f2.y, s2);
            s2 = fmaf(bw.z, f2.z, s2); s2 = fmaf(bw.w, f2.w, s2);
            float s3 = bw.x * f3.x; s3 = fmaf(bw.y, f3.y, s3);
            s3 = fmaf(bw.z, f3.z, s3); s3 = fmaf(bw.w, f3.w, s3);
            a0 = fmaf(aw, s0, a0);
            a1 = fmaf(aw, s1, a1);
            a2 = fmaf(aw, s2, a2);
            a3 = fmaf(aw, s3, a3);
        }

        // four independent butterfly reductions (pipelined)
        #pragma unroll
        for (int o = 16; o; o >>= 1) {
            a0 += __shfl_xor_sync(0xffffffffu, a0, o);
            a1 += __shfl_xor_sync(0xffffffffu, a1, o);
            a2 += __shfl_xor_sync(0xffffffffu, a2, o);
            a3 += __shfl_xor_sync(0xffffffffu, a3, o);
        }

        if (lane == 0) {
            float* op = out + (size_t)roi * C_CH + cb0;
            atomicAdd(op + 0, a0);
            atomicAdd(op + 1, a1);
            atomicAdd(op + 2, a2);
            atomicAdd(op + 3, a3);
        }
    }
}

extern "C" void kernel_launch(void* const* d_in, const int* in_sizes, int n_in,
                              void* d_out, int out_size)
{
    const float* feat = (const float*)d_in[0];   // (4, 256, 128, 128) fp32
    const float* rois = (const float*)d_in[1];   // (N, 6) fp32
    float* out = (float*)d_out;

    const int n_rois = in_sizes[1] / 6;          // 512
    (void)n_in; (void)out_size;

    roi_setup_kernel<<<n_rois, 32>>>(rois, out, n_rois);

    dim3 grid(HWD / RS, C_CH / CB, 4);           // (8, 64, 4)
    roi_tile_kernel<<<grid, NTHREADS>>>(feat, out, n_rois);
}

// round 12
// speedup vs baseline: 1.2055x; 1.1171x over previous
#include <cuda_runtime.h>
#include <cuda_fp16.h>

// ROIAlign(7x7, sr=2) + global avg pool, separable-weight formulation with
// fp16 shared-memory feature tiling.
//
// out[roi,ch] = sum_r a[r] * sum_c b[c] * F[bi,ch,r,c]; a/b are the y/x
// bilinear weight marginals (b pre-scaled by 1/196).
//
// R11: fp16 tiles. Feature values are converted fp32->fp16 in-register
// during tile staging (no extra global traffic); all ROI accumulation math
// stays fp32. LDS bytes through the shared pipe halve; one LDS.128 yields
// 8 columns, so 8 channels per block amortize per-ROI overhead over wider
// iterations. Tile = 8ch x 16row x 136col fp16 (35KB, conflict-free).

#define C_CH   256
#define HWD    128
#define RS     16           // rows per strip
#define CB     8            // channels per block
#define TCOLS  136          // padded tile row (17 x 16B granules, odd)
#define NTHREADS 256
#define CH_TILE_B (RS * TCOLS * 2)   // 4352 bytes per channel slab

__device__ __align__(16) float g_a[512 * 128];
__device__ __align__(16) float g_b[512 * 192];
__device__ int4 g_meta[512];     // {bi, rlo, rhi, base8 | nch8<<8}

// ---------------------------------------------------------------------------
// Setup: one 32-thread block per ROI.
// ---------------------------------------------------------------------------
__global__ void roi_setup_kernel(const float* __restrict__ rois,
                                 float* __restrict__ out, int n_rois)
{
    __shared__ float sa[128];
    __shared__ float sb[192];
    __shared__ int rlo_s, rhi_s, clo_s, chi_s;

    const int roi  = blockIdx.x;
    const int lane = threadIdx.x;

    if (lane == 0) { rlo_s = 1 << 30; rhi_s = -1; clo_s = 1 << 30; chi_s = -1; }
    for (int i = lane; i < 192; i += 32) { if (i < 128) sa[i] = 0.f; sb[i] = 0.f; }
    __syncwarp();

    // Lanes 0..13 = 14 y-samples, lanes 16..29 = 14 x-samples.
    const bool isY = (lane < 14);
    const bool isX = (lane >= 16 && lane < 30);
    if (isY || isX) {
        const int s = isY ? lane : lane - 16;
        const float cx = rois[roi * 6 + 2];
        const float cy = rois[roi * 6 + 3];
        const float w  = rois[roi * 6 + 4];
        const float h  = rois[roi * 6 + 5];
        // Reference rounds the scaled corners through fp16.
        const float x1 = __half2float(__float2half_rn((cx - 0.5f * w) * 128.f));
        const float x2 = __half2float(__float2half_rn((cx + 0.5f * w) * 128.f));
        const float y1 = __half2float(__float2half_rn((cy - 0.5f * h) * 128.f));
        const float y2 = __half2float(__float2half_rn((cy + 0.5f * h) * 128.f));
        const float rw = fmaxf(x2 - x1, 1.f);
        const float rh = fmaxf(y2 - y1, 1.f);

        const float off   = 0.25f + 0.5f * (float)s;   // p + (sub+0.5)/2
        const float start = isY ? y1 : x1;
        const float ext   = isY ? rh : rw;
        const float coord = start + off * (ext / 7.f);

        if (coord > -1.f && coord < 128.f) {
            const float cl = fminf(fmaxf(coord, 0.f), 127.f);
            const int   i0 = (int)floorf(cl);
            const int   i1 = min(i0 + 1, HWD - 1);
            const float l  = cl - (float)i0;
            const float hi = 1.f - l;
            if (isY) {
                atomicAdd(&sa[i0], hi);
                atomicAdd(&sa[i1], l);
                atomicMin(&rlo_s, i0);
                atomicMax(&rhi_s, i1);
            } else {
                const float inv = 1.f / 196.f;  // fold in the mean
                atomicAdd(&sb[i0], hi * inv);
                atomicAdd(&sb[i1], l * inv);
                atomicMin(&clo_s, i0);
                atomicMax(&chi_s, i1);
            }
        }
    }
    __syncwarp();

    for (int i = lane; i < 128; i += 32) g_a[roi * 128 + i] = sa[i];
    for (int i = lane; i < 192; i += 32) g_b[roi * 192 + i] = sb[i];
    // zero output feats (main kernel accumulates with atomics)
    for (int i = lane; i < C_CH; i += 32) out[(size_t)roi * C_CH + i] = 0.f;

    if (lane == 0) {
        out[(size_t)n_rois * C_CH + roi] = rois[roi * 6 + 1];   // gt
        int base8 = 0, nch8 = 0;
        if (rhi_s >= rlo_s && chi_s >= clo_s) {
            base8 = clo_s & ~7;
            nch8  = ((chi_s - base8) >> 3) + 1;   // 8-col chunks (<=8)
        }
        g_meta[roi] = make_int4((int)rois[roi * 6 + 0], rlo_s, rhi_s,
                                base8 | (nch8 << 8));
    }
}

// ---------------------------------------------------------------------------
// Main: fp16-tile staged accumulation.
// ---------------------------------------------------------------------------
__global__ __launch_bounds__(NTHREADS, 4)
void roi_tile_kernel(const float* __restrict__ feat,
                     float* __restrict__ out, int n_rois)
{
    __shared__ __align__(16) __half tile[CB][RS][TCOLS];
    __shared__ int list_sh[512];
    __shared__ int cnt_sh;

    const int tid = threadIdx.x;
    const int rs0 = blockIdx.x * RS;
    const int cb0 = blockIdx.y * CB;
    const int bi  = blockIdx.z;

    if (tid == 0) cnt_sh = 0;

    // Stage the 8ch x 16row x 128col tile, converting fp32 -> fp16.
    // 4096 float4 slots; each thread handles 16 (coalesced LDG.128 + STS.64).
    const float* fsrc = feat + ((size_t)bi * C_CH + cb0) * (HWD * HWD)
                             + (size_t)rs0 * HWD;
    #pragma unroll
    for (int k = 0; k < 16; ++k) {
        const int idx = tid + k * NTHREADS;       // 0..4095
        const int ch  = idx >> 9;                 // 512 float4 per channel
        const int r   = (idx >> 5) & 15;
        const int c4  = idx & 31;
        const float4 v = *(const float4*)(fsrc + (size_t)ch * (HWD * HWD)
                                               + r * HWD + c4 * 4);
        __half2 h0 = __floats2half2_rn(v.x, v.y);
        __half2 h1 = __floats2half2_rn(v.z, v.w);
        *(__half2*)&tile[ch][r][c4 * 4 + 0] = h0;
        *(__half2*)&tile[ch][r][c4 * 4 + 2] = h1;
    }
    __syncthreads();

    // Build the list of ROIs intersecting this (batch, strip).
    for (int t = tid; t < n_rois; t += NTHREADS) {
        const int4 m = g_meta[t];
        const int nch8 = m.w >> 8;
        if (m.x == bi && nch8 > 0 && m.y <= rs0 + RS - 1 && m.z >= rs0) {
            const int p = atomicAdd(&cnt_sh, 1);
            if (p < 512) list_sh[p] = t;
        }
    }
    __syncthreads();

    const int warp = tid >> 5;
    const int lane = tid & 31;
    const int n = min(cnt_sh, 512);

    for (int li = warp; li < n; li += 8) {
        const int roi = list_sh[li];
        const int4 m = g_meta[roi];
        const int base8 = m.w & 0xff;
        const int nch8  = m.w >> 8;
        const int r0 = max(m.y, rs0);
        const int r1 = min(m.z, rs0 + RS - 1);
        const int nrs = r1 - r0 + 1;

        const int ncp   = (nch8 <= 1) ? 1 : (1 << (32 - __clz(nch8 - 1)));
        const int logn  = 31 - __clz(ncp);
        const int rpi   = 32 >> logn;            // rows per iteration (>=4)
        const int chunk = lane & (ncp - 1);
        const int rsub  = lane >> logn;

        // Hoisted column weights for this lane's 8-column chunk.
        const int colv8 = base8 + 8 * chunk;     // can exceed 128 when ncp
        const float* gb = &g_b[roi * 192 + colv8];   // rounds up: g_b padded 0
        const float4 bwA = *(const float4*)(gb);
        const float4 bwB = *(const float4*)(gb + 4);
        const int ceff = min(colv8, HWD - 8);    // weight is 0 there anyway

        const float* ap = &g_a[roi * 128 + r0];
        const char* tp = (const char*)&tile[0][0][0]
                       + ((size_t)(r0 - rs0) * TCOLS + ceff) * 2;

        float a0 = 0.f, a1 = 0.f, a2 = 0.f, a3 = 0.f;
        float a4 = 0.f, a5 = 0.f, a6 = 0.f, a7 = 0.f;
        #pragma unroll 1
        for (int i = rsub; i < nrs; i += rpi) {
            const float aw = __ldg(ap + i);
            const char* p = tp + (size_t)i * (TCOLS * 2);
            #pragma unroll
            for (int c = 0; c < 8; ++c) {
                const uint4 u = *(const uint4*)(p + c * CH_TILE_B);
                const float2 f0 = __half22float2(*(const __half2*)&u.x);
                const float2 f1 = __half22float2(*(const __half2*)&u.y);
                const float2 f2 = __half22float2(*(const __half2*)&u.z);
                const float2 f3 = __half22float2(*(const __half2*)&u.w);
                float s = bwA.x * f0.x;
                s = fmaf(bwA.y, f0.y, s);
                s = fmaf(bwA.z, f1.x, s);
                s = fmaf(bwA.w, f1.y, s);
                s = fmaf(bwB.x, f2.x, s);
                s = fmaf(bwB.y, f2.y, s);
                s = fmaf(bwB.z, f3.x, s);
                s = fmaf(bwB.w, f3.y, s);
                switch (c) {
                    case 0: a0 = fmaf(aw, s, a0); break;
                    case 1: a1 = fmaf(aw, s, a1); break;
                    case 2: a2 = fmaf(aw, s, a2); break;
                    case 3: a3 = fmaf(aw, s, a3); break;
                    case 4: a4 = fmaf(aw, s, a4); break;
                    case 5: a5 = fmaf(aw, s, a5); break;
                    case 6: a6 = fmaf(aw, s, a6); break;
                    case 7: a7 = fmaf(aw, s, a7); break;
                }
            }
        }

        // eight independent butterfly reductions (pipelined)
        #pragma unroll
        for (int o = 16; o; o >>= 1) {
            a0 += __shfl_xor_sync(0xffffffffu, a0, o);
            a1 += __shfl_xor_sync(0xffffffffu, a1, o);
            a2 += __shfl_xor_sync(0xffffffffu, a2, o);
            a3 += __shfl_xor_sync(0xffffffffu, a3, o);
            a4 += __shfl_xor_sync(0xffffffffu, a4, o);
            a5 += __shfl_xor_sync(0xffffffffu, a5, o);
            a6 += __shfl_xor_sync(0xffffffffu, a6, o);
            a7 += __shfl_xor_sync(0xffffffffu, a7, o);
        }

        if (lane == 0) {
            float* op = out + (size_t)roi * C_CH + cb0;
            atomicAdd(op + 0, a0);
            atomicAdd(op + 1, a1);
            atomicAdd(op + 2, a2);
            atomicAdd(op + 3, a3);
            atomicAdd(op + 4, a4);
            atomicAdd(op + 5, a5);
            atomicAdd(op + 6, a6);
            atomicAdd(op + 7, a7);
        }
    }
}

extern "C" void kernel_launch(void* const* d_in, const int* in_sizes, int n_in,
                              void* d_out, int out_size)
{
    const float* feat = (const float*)d_in[0];   // (4, 256, 128, 128) fp32
    const float* rois = (const float*)d_in[1];   // (N, 6) fp32
    float* out = (float*)d_out;

    const int n_rois = in_sizes[1] / 6;          // 512
    (void)n_in; (void)out_size;

    roi_setup_kernel<<<n_rois, 32>>>(rois, out, n_rois);

    dim3 grid(HWD / RS, C_CH / CB, 4);           // (8, 32, 4)
    roi_tile_kernel<<<grid, NTHREADS>>>(feat, out, n_rois);
}